// round 1
// baseline (speedup 1.0000x reference)
#include <cuda_runtime.h>
#include <math.h>

#define NB 256        // batch
#define NT 64         // timesteps
#define NACT 6
#define SD 1024       // STOCH*DISC
#define GDIM 3072
#define ZA_LD 1040    // 1030 padded to 16B-aligned rows

// ---------------- scratch (device globals: no allocation allowed) ----------------
__device__ float g_ZA[NB * ZA_LD];     // [z (1024) | action (6) | pad]
__device__ float g_H1[NB * 1024];      // imagine hidden
__device__ float g_IB[NB * 2048];      // [inp (1024) | belief (1024)]
__device__ float g_G [NB * GDIM];     // raw GRU gates
__device__ float g_OB[NB * 2048];      // [obs (1024) | belief (1024)]
__device__ float g_HP[NB * 1024];      // prior hidden
__device__ float g_HO[NB * 1024];      // post hidden
__device__ float g_PL[NB * 1024];      // prior logits
__device__ float g_QL[NB * 1024];      // post logits

// ---------------- helpers ----------------
__device__ __forceinline__ float warp_sum(float v) {
#pragma unroll
    for (int o = 16; o; o >>= 1) v += __shfl_xor_sync(0xffffffffu, v, o);
    return v;
}
__device__ __forceinline__ float warp_max(float v) {
#pragma unroll
    for (int o = 16; o; o >>= 1) v = fmaxf(v, __shfl_xor_sync(0xffffffffu, v, o));
    return v;
}

// precise transcendentals via double path (immune to --use_fast_math rewrites)
__device__ __forceinline__ float silu_f(float x) {
    double e = exp(-(double)x);
    return (float)((double)x / (1.0 + e));
}
__device__ __forceinline__ float sigmoid_f(float x) {
    return (float)(1.0 / (1.0 + exp(-(double)x)));
}

// ---------------- init: z0 -> ZA, b0 -> IB belief half ----------------
__global__ void init_kernel(const float* __restrict__ z0, const float* __restrict__ b0) {
    int i = blockIdx.x * blockDim.x + threadIdx.x;
    if (i < NB * 1024) {
        int r = i >> 10, c = i & 1023;
        g_ZA[r * ZA_LD + c] = z0[i];
        g_IB[r * 2048 + 1024 + c] = b0[i];
    }
}

// ---------------- per-step prep: obs_t -> OB[:, :1024], actions_t -> ZA[:,1024:1030] ----------------
__global__ void prep_kernel(const float* __restrict__ actions_t, const float* __restrict__ obs_t) {
    int i = blockIdx.x * blockDim.x + threadIdx.x;
    const int n1 = NB * 1024;
    if (i < n1) {
        int r = i >> 10, c = i & 1023;
        g_OB[r * 2048 + c] = obs_t[i];
    } else {
        int j = i - n1;
        if (j < NB * NACT) {
            int r = j / NACT, c = j - r * NACT;
            g_ZA[r * ZA_LD + 1024 + c] = actions_t[j];
        }
    }
}

// ---------------- GEMM: C = act(A @ W + bias), A row-major (M=256 fixed by grid), W row-major KxN
// BM=64, BN=64, BK=16, 256 threads, 4x4 microtile ----------------
template <int DO_SILU>
__global__ void gemm_kernel(const float* __restrict__ A, int lda,
                            const float* __restrict__ W, int ldw,
                            const float* __restrict__ bias,
                            float* __restrict__ C, int ldc, int K) {
    __shared__ float As[16][64];
    __shared__ float Bs[16][64];
    const int tid = threadIdx.x;
    const int m0 = blockIdx.y * 64, n0 = blockIdx.x * 64;
    const int ar = tid >> 2, ac = (tid & 3) << 2;     // A tile: row ar (0..63), k-cols ac..ac+3
    const int br = tid >> 4, bc = (tid & 15) << 2;    // W tile: k-row br (0..15), n-cols bc..bc+3
    const int ty = tid >> 4, tx = tid & 15;

    float acc[4][4] = {};
    const float* Ap = A + (size_t)(m0 + ar) * lda;

    for (int k0 = 0; k0 < K; k0 += 16) {
        if (k0 + 16 <= K) {
            float4 a4 = *(const float4*)(Ap + k0 + ac);
            As[ac + 0][ar] = a4.x; As[ac + 1][ar] = a4.y;
            As[ac + 2][ar] = a4.z; As[ac + 3][ar] = a4.w;
            *(float4*)&Bs[br][bc] = *(const float4*)(W + (size_t)(k0 + br) * ldw + n0 + bc);
        } else {
#pragma unroll
            for (int j = 0; j < 4; j++) {
                int kk = k0 + ac + j;
                As[ac + j][ar] = (kk < K) ? Ap[kk] : 0.0f;
            }
            float4 b4 = make_float4(0.f, 0.f, 0.f, 0.f);
            if (k0 + br < K) b4 = *(const float4*)(W + (size_t)(k0 + br) * ldw + n0 + bc);
            *(float4*)&Bs[br][bc] = b4;
        }
        __syncthreads();
#pragma unroll
        for (int kk = 0; kk < 16; kk++) {
            float4 a = *(const float4*)&As[kk][ty * 4];
            float4 b = *(const float4*)&Bs[kk][tx * 4];
            acc[0][0] += a.x * b.x; acc[0][1] += a.x * b.y; acc[0][2] += a.x * b.z; acc[0][3] += a.x * b.w;
            acc[1][0] += a.y * b.x; acc[1][1] += a.y * b.y; acc[1][2] += a.y * b.z; acc[1][3] += a.y * b.w;
            acc[2][0] += a.z * b.x; acc[2][1] += a.z * b.y; acc[2][2] += a.z * b.z; acc[2][3] += a.z * b.w;
            acc[3][0] += a.w * b.x; acc[3][1] += a.w * b.y; acc[3][2] += a.w * b.z; acc[3][3] += a.w * b.w;
        }
        __syncthreads();
    }

#pragma unroll
    for (int i = 0; i < 4; i++) {
        int m = m0 + ty * 4 + i;
#pragma unroll
        for (int j = 0; j < 4; j++) {
            int n = n0 + tx * 4 + j;
            float v = acc[i][j];
            if (bias) v += bias[n];
            if (DO_SILU) v = silu_f(v);
            C[(size_t)m * ldc + n] = v;
        }
    }
}

// ---------------- LayerNorm(3072, eps=1e-3) + GRU update, one block per batch row ----------------
__global__ void lngru_kernel(const float* __restrict__ ln_scale, const float* __restrict__ ln_bias) {
    const int row = blockIdx.x;
    const int tid = threadIdx.x;
    __shared__ float sh[8];
    __shared__ float bcast;

    const float* gr = g_G + (size_t)row * GDIM;
    float x[12];
    float s = 0.0f;
#pragma unroll
    for (int i = 0; i < 12; i++) { x[i] = gr[tid + i * 256]; s += x[i]; }

    // block sum (mean)
    s = warp_sum(s);
    if ((tid & 31) == 0) sh[tid >> 5] = s;
    __syncthreads();
    if (tid < 32) {
        float t = (tid < 8) ? sh[tid] : 0.0f;
        t = warp_sum(t);
        if (tid == 0) bcast = t;
    }
    __syncthreads();
    const float mu = __fdiv_rn(bcast, 3072.0f);
    __syncthreads();

    float v = 0.0f;
#pragma unroll
    for (int i = 0; i < 12; i++) { float d = x[i] - mu; v += d * d; }
    v = warp_sum(v);
    if ((tid & 31) == 0) sh[tid >> 5] = v;
    __syncthreads();
    if (tid < 32) {
        float t = (tid < 8) ? sh[tid] : 0.0f;
        t = warp_sum(t);
        if (tid == 0) bcast = t;
    }
    __syncthreads();
    const float var = __fdiv_rn(bcast, 3072.0f);
    const float denom = __fsqrt_rn(var + 1e-3f);

#pragma unroll
    for (int jj = 0; jj < 4; jj++) {
        int j = tid + jj * 256;
        float yr = __fdiv_rn(x[jj]     - mu, denom) * ln_scale[j]        + ln_bias[j];
        float yc = __fdiv_rn(x[jj + 4] - mu, denom) * ln_scale[j + 1024] + ln_bias[j + 1024];
        float yu = __fdiv_rn(x[jj + 8] - mu, denom) * ln_scale[j + 2048] + ln_bias[j + 2048];
        float reset = sigmoid_f(yr);
        float cand  = (float)tanh((double)(reset * yc));
        float upd   = sigmoid_f(yu - 1.0f);   // UPDATE_BIAS = -1
        float bprev = g_IB[(size_t)row * 2048 + 1024 + j];
        float bn = upd * cand + (1.0f - upd) * bprev;
        g_IB[(size_t)row * 2048 + 1024 + j] = bn;
        g_OB[(size_t)row * 2048 + 1024 + j] = bn;
    }
}

// ---------------- softmax/unimix/KL + gumbel-max sample -> z, loss; one block per batch row ----------------
__global__ void sample_kernel(const float* __restrict__ U_t, float* __restrict__ losses_t) {
    const int row = blockIdx.x;
    const int tid = threadIdx.x;
    const int warp = tid >> 5, lane = tid & 31;
    __shared__ float klsh[8];

    float klacc = 0.0f;
#pragma unroll
    for (int sg = 0; sg < 4; sg++) {
        const int s2 = warp * 4 + sg;                 // stoch group 0..31
        const int idx = row * 1024 + s2 * 32 + lane;  // category = lane

        float pl = fminf(fmaxf(g_PL[idx], -20.0f), 20.0f);
        float ql = fminf(fmaxf(g_QL[idx], -20.0f), 20.0f);

        float pm = warp_max(pl);
        float pe = (float)exp((double)(pl - pm));
        float ps = warp_sum(pe);
        float pp = __fdiv_rn(pe, ps) * 0.99f + (0.01f / 32.0f);

        float qm = warp_max(ql);
        float qe = (float)exp((double)(ql - qm));
        float qs = warp_sum(qe);
        float qp = __fdiv_rn(qe, qs) * 0.99f + (0.01f / 32.0f);

        float aq = qp + 1e-8f;
        float ap = pp + 1e-8f;
        klacc += qp * (float)(log((double)aq) - log((double)ap));

        // gumbel-max sample (first-index tie-break, matching jnp.argmax)
        float u = U_t[row * 1024 + s2 * 32 + lane];
        float gum = (float)(-log(-log((double)u + 1e-6) + 1e-6));
        float val = (float)log((double)fmaxf(qp, 1e-6f)) + gum;
        float bv = val; int bi = lane;
#pragma unroll
        for (int o = 16; o; o >>= 1) {
            float ov = __shfl_xor_sync(0xffffffffu, bv, o);
            int   oi = __shfl_xor_sync(0xffffffffu, bi, o);
            if (ov > bv || (ov == bv && oi < bi)) { bv = ov; bi = oi; }
        }
        float y = (lane == bi) ? 1.0f : 0.0f;
        // straight-through value: (y + p) - p  (matches reference fp32 arithmetic exactly)
        float z = __fsub_rn(__fadd_rn(y, qp), qp);
        g_ZA[(size_t)row * ZA_LD + s2 * 32 + lane] = z;
    }

    float w = warp_sum(klacc);
    if (lane == 0) klsh[warp] = w;
    __syncthreads();
    if (tid == 0) {
        float kl = 0.0f;
#pragma unroll
        for (int i = 0; i < 8; i++) kl += klsh[i];
        float m = fmaxf(kl, 0.1f);               // kl_dyn == kl_rep numerically
        losses_t[row] = 1.0f * m + 0.1f * m;     // DYN_SCALE*dyn + REP_SCALE*rep
    }
}

// ---------------- launch ----------------
extern "C" void kernel_launch(void* const* d_in, const int* in_sizes, int n_in,
                              void* d_out, int out_size) {
    const float* b0       = (const float*)d_in[0];
    const float* z0       = (const float*)d_in[1];
    const float* actions  = (const float*)d_in[2];
    const float* obs      = (const float*)d_in[3];
    const float* u_noise  = (const float*)d_in[4];
    const float* Wi1      = (const float*)d_in[5];
    const float* bi1      = (const float*)d_in[6];
    const float* Wi2      = (const float*)d_in[7];
    const float* bi2      = (const float*)d_in[8];
    const float* Wg       = (const float*)d_in[9];
    const float* ln_scale = (const float*)d_in[10];
    const float* ln_bias  = (const float*)d_in[11];
    const float* Wo1      = (const float*)d_in[12];
    const float* bo1      = (const float*)d_in[13];
    const float* Wo2      = (const float*)d_in[14];
    const float* bo2      = (const float*)d_in[15];
    const float* Wp1      = (const float*)d_in[16];
    const float* bp1      = (const float*)d_in[17];
    const float* Wp2      = (const float*)d_in[18];
    const float* bp2      = (const float*)d_in[19];
    float* out = (float*)d_out;

    float *pZA, *pH1, *pIB, *pG, *pOB, *pHP, *pHO, *pPL, *pQL;
    cudaGetSymbolAddress((void**)&pZA, g_ZA);
    cudaGetSymbolAddress((void**)&pH1, g_H1);
    cudaGetSymbolAddress((void**)&pIB, g_IB);
    cudaGetSymbolAddress((void**)&pG,  g_G);
    cudaGetSymbolAddress((void**)&pOB, g_OB);
    cudaGetSymbolAddress((void**)&pHP, g_HP);
    cudaGetSymbolAddress((void**)&pHO, g_HO);
    cudaGetSymbolAddress((void**)&pPL, g_PL);
    cudaGetSymbolAddress((void**)&pQL, g_QL);

    init_kernel<<<(NB * 1024 + 255) / 256, 256>>>(z0, b0);

    const dim3 gN1024(16, 4);   // N=1024 GEMMs
    const dim3 gN3072(48, 4);   // GRU gate GEMM

    for (int t = 0; t < NT; t++) {
        prep_kernel<<<(NB * 1024 + NB * NACT + 255) / 256, 256>>>(
            actions + (size_t)t * NB * NACT, obs + (size_t)t * NB * 1024);

        // imagine MLP: h1 = silu([z|a] @ Wi1 + bi1); inp = h1 @ Wi2 + bi2
        gemm_kernel<1><<<gN1024, 256>>>(pZA, ZA_LD, Wi1, 1024, bi1, pH1, 1024, 1030);
        gemm_kernel<0><<<gN1024, 256>>>(pH1, 1024, Wi2, 1024, bi2, pIB, 2048, 1024);

        // GRU gates: G = [inp|b] @ Wg (no bias), then LN + GRU update -> belief
        gemm_kernel<0><<<gN3072, 256>>>(pIB, 2048, Wg, 3072, nullptr, pG, 3072, 2048);
        lngru_kernel<<<NB, 256>>>(ln_scale, ln_bias);

        // prior MLP on b_new
        gemm_kernel<1><<<gN1024, 256>>>(pIB + 1024, 2048, Wp1, 1024, bp1, pHP, 1024, 1024);
        gemm_kernel<0><<<gN1024, 256>>>(pHP, 1024, Wp2, 1024, bp2, pPL, 1024, 1024);

        // posterior MLP on [obs|b_new]
        gemm_kernel<1><<<gN1024, 256>>>(pOB, 2048, Wo1, 1024, bo1, pHO, 1024, 2048);
        gemm_kernel<0><<<gN1024, 256>>>(pHO, 1024, Wo2, 1024, bo2, pQL, 1024, 1024);

        // probs + KL loss + gumbel sample -> z for next step
        sample_kernel<<<NB, 256>>>(u_noise + (size_t)t * NB * 1024, out + (size_t)t * NB);
    }
}

// round 2
// speedup vs baseline: 1.3753x; 1.3753x over previous
#include <cuda_runtime.h>
#include <math.h>

#define NB 256        // batch
#define NT 64         // timesteps
#define NACT 6
#define GDIM 3072
#define ZA_LD 1040    // 1024 z + 6 act + 10 zero pad (K=1040 multiple of 16)
#define WI1_K 1040

// ---------------- scratch (device globals: no allocation allowed) ----------------
__device__ float g_ZA[NB * ZA_LD];       // [z (1024) | action (6) | zero pad]
__device__ float g_H1[NB * 1024];        // imagine hidden
__device__ float g_IB[NB * 2048];        // [inp (1024) | belief (1024)]
__device__ float g_G [NB * GDIM];        // raw GRU gates
__device__ float g_OB[NB * 2048];        // [obs (1024) | belief (1024)]
__device__ float g_HP[NB * 1024];        // prior hidden
__device__ float g_HO[NB * 1024];        // post hidden
__device__ float g_PL[NB * 1024];        // prior logits
__device__ float g_QL[NB * 1024];        // post logits
__device__ float g_Wi1p[WI1_K * 1024];   // Wi1 zero-padded to K=1040 rows

// ---------------- helpers ----------------
__device__ __forceinline__ float warp_sum(float v) {
#pragma unroll
    for (int o = 16; o; o >>= 1) v += __shfl_xor_sync(0xffffffffu, v, o);
    return v;
}
__device__ __forceinline__ float warp_max(float v) {
#pragma unroll
    for (int o = 16; o; o >>= 1) v = fmaxf(v, __shfl_xor_sync(0xffffffffu, v, o));
    return v;
}

// precise transcendentals via double path (immune to --use_fast_math rewrites)
__device__ __forceinline__ float silu_f(float x) {
    double e = exp(-(double)x);
    return (float)((double)x / (1.0 + e));
}
__device__ __forceinline__ float sigmoid_f(float x) {
    return (float)(1.0 / (1.0 + exp(-(double)x)));
}

// ---------------- packed f32x2 via PTX (per-lane identical to FFMA rounding) ----
__device__ __forceinline__ double dup2(float x) {
    double r; asm("mov.b64 %0, {%1,%1};" : "=d"(r) : "f"(x)); return r;
}
__device__ __forceinline__ double ffma2(double a, double b, double c) {
    double d; asm("fma.rn.f32x2 %0, %1, %2, %3;" : "=d"(d) : "d"(a), "d"(b), "d"(c)); return d;
}
__device__ __forceinline__ float2 unpack2(double p) {
    float2 f; asm("mov.b64 {%0,%1}, %2;" : "=f"(f.x), "=f"(f.y) : "d"(p)); return f;
}

__device__ __forceinline__ void cp16(void* smem, const void* g) {
    unsigned s = (unsigned)__cvta_generic_to_shared(smem);
    asm volatile("cp.async.ca.shared.global [%0], [%1], 16;\n" :: "r"(s), "l"(g));
}
__device__ __forceinline__ void cp_commit() { asm volatile("cp.async.commit_group;\n"); }
__device__ __forceinline__ void cp_wait0()  { asm volatile("cp.async.wait_group 0;\n"); }

// ---------------- init: z0 -> ZA (+ zero pad cols), b0 -> IB belief half --------
__global__ void init_kernel(const float* __restrict__ z0, const float* __restrict__ b0) {
    int i = blockIdx.x * blockDim.x + threadIdx.x;
    if (i < NB * 1024) {
        int r = i >> 10, c = i & 1023;
        g_ZA[r * ZA_LD + c] = z0[i];
        g_IB[r * 2048 + 1024 + c] = b0[i];
        if (c >= 1024 - 10) g_ZA[r * ZA_LD + (c + 16)] = 0.0f;  // cols 1030..1039
    }
}

// ---------------- Wi1 zero-pad copy (runs once per launch) ----------------------
__global__ void padw_kernel(const float* __restrict__ Wi1) {
    int i = blockIdx.x * blockDim.x + threadIdx.x;
    if (i < WI1_K * 1024) {
        int r = i >> 10;
        g_Wi1p[i] = (r < 1030) ? Wi1[i] : 0.0f;
    }
}

// ---------------- per-step prep ----------------
__global__ void prep_kernel(const float* __restrict__ actions_t, const float* __restrict__ obs_t) {
    int i = blockIdx.x * blockDim.x + threadIdx.x;
    const int n1 = NB * 1024;
    if (i < n1) {
        int r = i >> 10, c = i & 1023;
        g_OB[r * 2048 + c] = obs_t[i];
    } else {
        int j = i - n1;
        if (j < NB * NACT) {
            int r = j / NACT, c = j - r * NACT;
            g_ZA[r * ZA_LD + 1024 + c] = actions_t[j];
        }
    }
}

// ---------------- GEMM problem descriptor ----------------
struct GP {
    const float* A; const float* W; const float* bias; float* C;
    int lda, ldw, ldc, K;
};

// C = act(A @ W + bias). BM=BN=64, BK=16, 256 thr, 4x4 microtile with FFMA2 over
// j-pairs. Double-buffered: cp.async for W tile, register-prefetched A tile.
// blockIdx.z selects between two independent problems.
template <int DO_SILU>
__global__ void __launch_bounds__(256) gemm2_kernel(GP p0, GP p1) {
    GP p = blockIdx.z ? p1 : p0;
    __shared__ float As[2][16][68];   // [k][m], stride 68: 16B-aligned rows, conflict-free
    __shared__ float Bs[2][16][64];   // [k][n]

    const int tid = threadIdx.x;
    const int m0 = blockIdx.y * 64, n0 = blockIdx.x * 64;
    const int ar = tid & 63, ac = (tid >> 6) << 2;    // A load: row ar, k-cols ac..ac+3
    const int br = tid >> 4, bc = (tid & 15) << 2;    // W load: k-row br, n-cols bc..bc+3
    const int ty = tid >> 4, tx = tid & 15;           // output microtile coords

    const float* Aptr = p.A + (size_t)(m0 + ar) * p.lda + ac;
    const float* Wptr = p.W + (size_t)br * p.ldw + n0 + bc;

    double acc[4][2];
#pragma unroll
    for (int i = 0; i < 4; i++) { acc[i][0] = dup2(0.0f); acc[i][1] = dup2(0.0f); }

    const int ntiles = p.K >> 4;

    // prologue: fill buffer 0
    {
        float4 a = *(const float4*)Aptr;
        cp16(&Bs[0][br][bc], Wptr);
        cp_commit();
        As[0][ac + 0][ar] = a.x; As[0][ac + 1][ar] = a.y;
        As[0][ac + 2][ar] = a.z; As[0][ac + 3][ar] = a.w;
        cp_wait0();
    }
    __syncthreads();

    for (int t = 0; t < ntiles; t++) {
        const int cur = t & 1, nxt = cur ^ 1;
        const bool more = (t + 1) < ntiles;
        float4 ap;
        if (more) {
            ap = *(const float4*)(Aptr + (t + 1) * 16);
            cp16(&Bs[nxt][br][bc], Wptr + (size_t)(t + 1) * 16 * p.ldw);
            cp_commit();
        }
#pragma unroll
        for (int kk = 0; kk < 16; kk++) {
            float4 av = *(const float4*)&As[cur][kk][ty * 4];
            double2 bv = *(const double2*)&Bs[cur][kk][tx * 4];
            double a0 = dup2(av.x), a1 = dup2(av.y), a2 = dup2(av.z), a3 = dup2(av.w);
            acc[0][0] = ffma2(a0, bv.x, acc[0][0]); acc[0][1] = ffma2(a0, bv.y, acc[0][1]);
            acc[1][0] = ffma2(a1, bv.x, acc[1][0]); acc[1][1] = ffma2(a1, bv.y, acc[1][1]);
            acc[2][0] = ffma2(a2, bv.x, acc[2][0]); acc[2][1] = ffma2(a2, bv.y, acc[2][1]);
            acc[3][0] = ffma2(a3, bv.x, acc[3][0]); acc[3][1] = ffma2(a3, bv.y, acc[3][1]);
        }
        if (more) {
            As[nxt][ac + 0][ar] = ap.x; As[nxt][ac + 1][ar] = ap.y;
            As[nxt][ac + 2][ar] = ap.z; As[nxt][ac + 3][ar] = ap.w;
            cp_wait0();
        }
        __syncthreads();
    }

    // epilogue
#pragma unroll
    for (int i = 0; i < 4; i++) {
        const int m = m0 + ty * 4 + i;
        float* Crow = p.C + (size_t)m * p.ldc + n0 + tx * 4;
#pragma unroll
        for (int jp = 0; jp < 2; jp++) {
            float2 v = unpack2(acc[i][jp]);
            if (p.bias) {
                v.x += p.bias[n0 + tx * 4 + jp * 2 + 0];
                v.y += p.bias[n0 + tx * 4 + jp * 2 + 1];
            }
            if (DO_SILU) { v.x = silu_f(v.x); v.y = silu_f(v.y); }
            *(float2*)(Crow + jp * 2) = v;
        }
    }
}

// ---------------- LayerNorm(3072, eps=1e-3) + GRU update ----------------
__global__ void lngru_kernel(const float* __restrict__ ln_scale, const float* __restrict__ ln_bias) {
    const int row = blockIdx.x;
    const int tid = threadIdx.x;
    __shared__ float sh[8];
    __shared__ float bcast;

    const float* gr = g_G + (size_t)row * GDIM;
    float x[12];
    float s = 0.0f;
#pragma unroll
    for (int i = 0; i < 12; i++) { x[i] = gr[tid + i * 256]; s += x[i]; }

    s = warp_sum(s);
    if ((tid & 31) == 0) sh[tid >> 5] = s;
    __syncthreads();
    if (tid < 32) {
        float t = (tid < 8) ? sh[tid] : 0.0f;
        t = warp_sum(t);
        if (tid == 0) bcast = t;
    }
    __syncthreads();
    const float mu = __fdiv_rn(bcast, 3072.0f);
    __syncthreads();

    float v = 0.0f;
#pragma unroll
    for (int i = 0; i < 12; i++) { float d = x[i] - mu; v += d * d; }
    v = warp_sum(v);
    if ((tid & 31) == 0) sh[tid >> 5] = v;
    __syncthreads();
    if (tid < 32) {
        float t = (tid < 8) ? sh[tid] : 0.0f;
        t = warp_sum(t);
        if (tid == 0) bcast = t;
    }
    __syncthreads();
    const float var = __fdiv_rn(bcast, 3072.0f);
    const float denom = __fsqrt_rn(var + 1e-3f);

#pragma unroll
    for (int jj = 0; jj < 4; jj++) {
        int j = tid + jj * 256;
        float yr = __fdiv_rn(x[jj]     - mu, denom) * ln_scale[j]        + ln_bias[j];
        float yc = __fdiv_rn(x[jj + 4] - mu, denom) * ln_scale[j + 1024] + ln_bias[j + 1024];
        float yu = __fdiv_rn(x[jj + 8] - mu, denom) * ln_scale[j + 2048] + ln_bias[j + 2048];
        float reset = sigmoid_f(yr);
        float cand  = (float)tanh((double)(reset * yc));
        float upd   = sigmoid_f(yu - 1.0f);   // UPDATE_BIAS = -1
        float bprev = g_IB[(size_t)row * 2048 + 1024 + j];
        float bn = upd * cand + (1.0f - upd) * bprev;
        g_IB[(size_t)row * 2048 + 1024 + j] = bn;
        g_OB[(size_t)row * 2048 + 1024 + j] = bn;
    }
}

// ---------------- softmax/unimix/KL + gumbel-max sample ----------------
__global__ void sample_kernel(const float* __restrict__ U_t, float* __restrict__ losses_t) {
    const int row = blockIdx.x;
    const int tid = threadIdx.x;
    const int warp = tid >> 5, lane = tid & 31;
    __shared__ float klsh[8];

    float klacc = 0.0f;
#pragma unroll
    for (int sg = 0; sg < 4; sg++) {
        const int s2 = warp * 4 + sg;
        const int idx = row * 1024 + s2 * 32 + lane;

        float pl = fminf(fmaxf(g_PL[idx], -20.0f), 20.0f);
        float ql = fminf(fmaxf(g_QL[idx], -20.0f), 20.0f);

        float pm = warp_max(pl);
        float pe = (float)exp((double)(pl - pm));
        float ps = warp_sum(pe);
        float pp = __fdiv_rn(pe, ps) * 0.99f + (0.01f / 32.0f);

        float qm = warp_max(ql);
        float qe = (float)exp((double)(ql - qm));
        float qs = warp_sum(qe);
        float qp = __fdiv_rn(qe, qs) * 0.99f + (0.01f / 32.0f);

        klacc += qp * (float)(log((double)(qp + 1e-8f)) - log((double)(pp + 1e-8f)));

        float u = U_t[row * 1024 + s2 * 32 + lane];
        float gum = (float)(-log(-log((double)u + 1e-6) + 1e-6));
        float val = (float)log((double)fmaxf(qp, 1e-6f)) + gum;
        float bv = val; int bi = lane;
#pragma unroll
        for (int o = 16; o; o >>= 1) {
            float ov = __shfl_xor_sync(0xffffffffu, bv, o);
            int   oi = __shfl_xor_sync(0xffffffffu, bi, o);
            if (ov > bv || (ov == bv && oi < bi)) { bv = ov; bi = oi; }
        }
        float y = (lane == bi) ? 1.0f : 0.0f;
        float z = __fsub_rn(__fadd_rn(y, qp), qp);
        g_ZA[(size_t)row * ZA_LD + s2 * 32 + lane] = z;
    }

    float w = warp_sum(klacc);
    if (lane == 0) klsh[warp] = w;
    __syncthreads();
    if (tid == 0) {
        float kl = 0.0f;
#pragma unroll
        for (int i = 0; i < 8; i++) kl += klsh[i];
        float m = fmaxf(kl, 0.1f);
        losses_t[row] = 1.0f * m + 0.1f * m;
    }
}

// ---------------- launch ----------------
extern "C" void kernel_launch(void* const* d_in, const int* in_sizes, int n_in,
                              void* d_out, int out_size) {
    const float* b0       = (const float*)d_in[0];
    const float* z0       = (const float*)d_in[1];
    const float* actions  = (const float*)d_in[2];
    const float* obs      = (const float*)d_in[3];
    const float* u_noise  = (const float*)d_in[4];
    const float* Wi1      = (const float*)d_in[5];
    const float* bi1      = (const float*)d_in[6];
    const float* Wi2      = (const float*)d_in[7];
    const float* bi2      = (const float*)d_in[8];
    const float* Wg       = (const float*)d_in[9];
    const float* ln_scale = (const float*)d_in[10];
    const float* ln_bias  = (const float*)d_in[11];
    const float* Wo1      = (const float*)d_in[12];
    const float* bo1      = (const float*)d_in[13];
    const float* Wo2      = (const float*)d_in[14];
    const float* bo2      = (const float*)d_in[15];
    const float* Wp1      = (const float*)d_in[16];
    const float* bp1      = (const float*)d_in[17];
    const float* Wp2      = (const float*)d_in[18];
    const float* bp2      = (const float*)d_in[19];
    float* out = (float*)d_out;

    float *pZA, *pH1, *pIB, *pG, *pOB, *pHP, *pHO, *pPL, *pQL, *pWi1p;
    cudaGetSymbolAddress((void**)&pZA, g_ZA);
    cudaGetSymbolAddress((void**)&pH1, g_H1);
    cudaGetSymbolAddress((void**)&pIB, g_IB);
    cudaGetSymbolAddress((void**)&pG,  g_G);
    cudaGetSymbolAddress((void**)&pOB, g_OB);
    cudaGetSymbolAddress((void**)&pHP, g_HP);
    cudaGetSymbolAddress((void**)&pHO, g_HO);
    cudaGetSymbolAddress((void**)&pPL, g_PL);
    cudaGetSymbolAddress((void**)&pQL, g_QL);
    cudaGetSymbolAddress((void**)&pWi1p, g_Wi1p);

    init_kernel<<<(NB * 1024 + 255) / 256, 256>>>(z0, b0);
    padw_kernel<<<(WI1_K * 1024 + 255) / 256, 256>>>(Wi1);

    const dim3 g1(16, 4, 1);     // single N=1024 GEMM
    const dim3 g1p(16, 4, 2);    // paired N=1024 GEMMs
    const dim3 gg(48, 4, 1);     // GRU gate GEMM (N=3072)

    for (int t = 0; t < NT; t++) {
        prep_kernel<<<(NB * 1024 + NB * NACT + 255) / 256, 256>>>(
            actions + (size_t)t * NB * NACT, obs + (size_t)t * NB * 1024);

        // imagine MLP
        GP i1{pZA, pWi1p, bi1, pH1, ZA_LD, 1024, 1024, WI1_K};
        gemm2_kernel<1><<<g1, 256>>>(i1, i1);
        GP i2{pH1, Wi2, bi2, pIB, 1024, 1024, 2048, 1024};
        gemm2_kernel<0><<<g1, 256>>>(i2, i2);

        // GRU gates + LN/GRU update
        GP gg_p{pIB, Wg, nullptr, pG, 2048, 3072, 3072, 2048};
        gemm2_kernel<0><<<gg, 256>>>(gg_p, gg_p);
        lngru_kernel<<<NB, 256>>>(ln_scale, ln_bias);

        // prior layer1 || posterior layer1 (both SiLU)
        GP p1{pIB + 1024, Wp1, bp1, pHP, 2048, 1024, 1024, 1024};
        GP o1{pOB,        Wo1, bo1, pHO, 2048, 1024, 1024, 2048};
        gemm2_kernel<1><<<g1p, 256>>>(p1, o1);

        // prior layer2 || posterior layer2
        GP p2{pHP, Wp2, bp2, pPL, 1024, 1024, 1024, 1024};
        GP o2{pHO, Wo2, bo2, pQL, 1024, 1024, 1024, 1024};
        gemm2_kernel<0><<<g1p, 256>>>(p2, o2);

        // probs + KL + gumbel sample
        sample_kernel<<<NB, 256>>>(u_noise + (size_t)t * NB * 1024, out + (size_t)t * NB);
    }
}